// round 4
// baseline (speedup 1.0000x reference)
#include <cuda_runtime.h>

#define NV 1022            // interior size
#define GV 1024            // full grid
#define SP 1024            // padded scratch row stride

#define T    4             // fused sweeps per kernel
#define CR   64            // compute-region side (per tile)
#define OUTT 56            // valid output side = CR - 2T
#define NT   19            // tiles per dim: ceil(1022/56)

#define UH 66              // smem tile rows  (CR + 2 ring)
#define UW 72              // smem row stride (floats), 16B-aligned cols
#define USZ (UH * UW)      // 4752 floats per buffer
#define SMEM_BYTES (3 * USZ * 4)   // U0, U1, Ks

#define HH2 (2.0f / (1023.0f * 1023.0f))   // 2*H^2

#define IDX(r, c) ((r) * UW + (c))

__device__ __align__(256) float g_bufA[8 * NV * SP];
__device__ __align__(256) float g_bufB[8 * NV * SP];

__device__ __forceinline__ float4 ld4g(const float* p) {
    return *reinterpret_cast<const float4*>(p);
}
__device__ __forceinline__ float4 ld4s(const float* p) {
    return *reinterpret_cast<const float4*>(p);
}
__device__ __forceinline__ void st4s(float* p, float4 v) {
    *reinterpret_cast<float4*>(p) = v;
}

// ---------------------------------------------------------------------------
// Fused 4-sweep Jacobi tile kernel.
//   VIN : input u is padded scratch (stride SP, vectorizable) vs `pre` (stride NV)
//   VOUT: output is padded scratch (stride SP, vectorizable) vs d_out (stride NV)
// Tile (ti,tj) output = interior rows [ti*56, +56) x cols [tj*56, +56).
// Compute region origin (interior coords): gi0 = ti*56-4, gj0 = tj*56-4.
// smem u mapping:  (li,lj) <-> interior (gi0-1+li, gj0-4+lj), li in [0,66), lj in [0,72)
// smem k mapping:  (r,c)   <-> full     (gi0+r,   gj0+c),     r,c in [0,66)
// ---------------------------------------------------------------------------
template<bool VIN, bool VOUT>
__global__ __launch_bounds__(256)
void fused_kernel(const float* __restrict__ uin,
                  float*       __restrict__ uout,
                  const float* __restrict__ kappa,
                  const float* __restrict__ f)
{
    extern __shared__ float smem[];
    float* U0 = smem;
    float* U1 = smem + USZ;
    float* KS = smem + 2 * USZ;

    const int tx = threadIdx.x;          // 0..15
    const int ty = threadIdx.y;          // 0..15
    const int tid = ty * 16 + tx;
    const int tj = blockIdx.x, ti = blockIdx.y, b = blockIdx.z;

    const int gi0 = ti * OUTT - T;       // compute-region origin (interior coords)
    const int gj0 = tj * OUTT - T;       // multiple of 4

    const size_t bK = (size_t)b * GV * GV;                    // kappa/f batch offset
    const size_t bU = VIN ? (size_t)b * NV * SP : (size_t)b * NV * NV;
    const size_t bO = VOUT ? (size_t)b * NV * SP : (size_t)b * NV * NV;

    // ---- cooperative load: kappa tile (66 x 66+, float4 rows) ----
    for (int idx = tid; idx < UH * 17; idx += 256) {
        int r = idx / 17, q = idx % 17;
        int c  = 4 * q;                  // local col 0..64 (covers 0..67)
        int fr = gi0 + r;                // full-grid row
        int fc = gj0 + c;                // full-grid col (mod 4 == 0)
        float4 v;
        if (fr >= 0 && fr < GV && fc >= 0 && fc + 3 < GV) {
            v = ld4g(kappa + bK + (size_t)fr * GV + fc);
        } else {
            float t[4];
            #pragma unroll
            for (int m = 0; m < 4; ++m) {
                int cc = fc + m;
                t[m] = (fr >= 0 && fr < GV && cc >= 0 && cc < GV)
                       ? kappa[bK + (size_t)fr * GV + cc] : 0.0f;
            }
            v = make_float4(t[0], t[1], t[2], t[3]);
        }
        st4s(KS + IDX(r, c), v);
    }

    // ---- cooperative load: u0 tile (66 x 72, ring zero-filled / real) ----
    for (int idx = tid; idx < UH * 18; idx += 256) {
        int li = idx / 18, q = idx % 18;
        int lj = 4 * q;                  // 0..68
        int i = gi0 - 1 + li;            // interior row
        int j = gj0 - 4 + lj;            // interior col (mod 4 == 0)
        float4 v;
        if (VIN) {
            if (i >= 0 && i < NV && j >= 0 && j + 3 < NV) {
                v = ld4g(uin + bU + (size_t)i * SP + j);
            } else {
                float t[4];
                #pragma unroll
                for (int m = 0; m < 4; ++m) {
                    int jj = j + m;
                    t[m] = (i >= 0 && i < NV && jj >= 0 && jj < NV)
                           ? uin[bU + (size_t)i * SP + jj] : 0.0f;
                }
                v = make_float4(t[0], t[1], t[2], t[3]);
            }
        } else {
            float t[4];
            #pragma unroll
            for (int m = 0; m < 4; ++m) {
                int jj = j + m;
                t[m] = (i >= 0 && i < NV && jj >= 0 && jj < NV)
                       ? uin[bU + (size_t)i * NV + jj] : 0.0f;
            }
            v = make_float4(t[0], t[1], t[2], t[3]);
        }
        st4s(U0 + IDX(li, lj), v);
    }

    __syncthreads();

    // ---- per-thread coefficients (held in registers across all sweeps) ----
    const int li0 = 1 + 4 * ty;          // owned rows li0..li0+3
    const int lj0 = 4 + 4 * tx;          // owned cols lj0..lj0+3

    float cN[4][4], cS[4][4], cW[4][4], cE[4][4], fp[4][4];
    #pragma unroll
    for (int rr = 0; rr < 4; ++rr) {
        #pragma unroll
        for (int cc = 0; cc < 4; ++cc) {
            int li = li0 + rr;
            int c  = lj0 + cc - 3;                 // kappa-tile col
            int i  = gi0 - 1 + li;                 // interior coords
            int j  = gj0 + c - 1;
            bool valid = (i >= 0 && i < NV && j >= 0 && j < NV);
            if (valid) {
                float kc = KS[IDX(li,     c)];
                float kn = KS[IDX(li - 1, c)];
                float ks = KS[IDX(li + 1, c)];
                float kw = KS[IDX(li,     c - 1)];
                float ke = KS[IDX(li,     c + 1)];
                float aN = kc + kn, aS = kc + ks, aW = kc + kw, aE = kc + ke;
                float inv = __frcp_rn((aN + aS) + (aW + aE));
                cN[rr][cc] = aN * inv;
                cS[rr][cc] = aS * inv;
                cW[rr][cc] = aW * inv;
                cE[rr][cc] = aE * inv;
                float fv = f[bK + (size_t)(i + 1) * GV + (j + 1)];
                fp[rr][cc] = fv * (HH2 * inv);
            } else {
                cN[rr][cc] = cS[rr][cc] = cW[rr][cc] = cE[rr][cc] = 0.0f;
                fp[rr][cc] = 0.0f;
            }
        }
    }

    // ---- T fused sweeps in shared memory ----
    float* src = U0;
    float* dst = U1;
    #pragma unroll
    for (int s = 0; s < T; ++s) {
        float4 up = ld4s(src + IDX(li0 - 1, lj0));
        float4 ce = ld4s(src + IDX(li0,     lj0));
        float  cl = src[IDX(li0, lj0 - 1)];
        float  cr = src[IDX(li0, lj0 + 4)];
        #pragma unroll
        for (int rr = 0; rr < 4; ++rr) {
            int li = li0 + rr;
            float4 dn = ld4s(src + IDX(li + 1, lj0));
            float  nl = src[IDX(li + 1, lj0 - 1)];
            float  nr = src[IDX(li + 1, lj0 + 4)];
            float4 r;
            r.x = fmaf(cN[rr][0], up.x, fp[rr][0]);
            r.x = fmaf(cS[rr][0], dn.x, r.x);
            r.x = fmaf(cW[rr][0], cl,   r.x);
            r.x = fmaf(cE[rr][0], ce.y, r.x);

            r.y = fmaf(cN[rr][1], up.y, fp[rr][1]);
            r.y = fmaf(cS[rr][1], dn.y, r.y);
            r.y = fmaf(cW[rr][1], ce.x, r.y);
            r.y = fmaf(cE[rr][1], ce.z, r.y);

            r.z = fmaf(cN[rr][2], up.z, fp[rr][2]);
            r.z = fmaf(cS[rr][2], dn.z, r.z);
            r.z = fmaf(cW[rr][2], ce.y, r.z);
            r.z = fmaf(cE[rr][2], ce.w, r.z);

            r.w = fmaf(cN[rr][3], up.w, fp[rr][3]);
            r.w = fmaf(cS[rr][3], dn.w, r.w);
            r.w = fmaf(cW[rr][3], ce.z, r.w);
            r.w = fmaf(cE[rr][3], cr,   r.w);

            st4s(dst + IDX(li, lj0), r);

            up = ce;
            cl = nl; cr = nr; ce = dn;
        }
        __syncthreads();
        float* tmp = src; src = dst; dst = tmp;
    }

    // ---- write valid 56x56 region (li 5..60, lj 8..63) ----
    for (int idx = tid; idx < OUTT * 14; idx += 256) {
        int row = idx / 14, q = idx % 14;
        int li = 1 + T + row;
        int lj = 4 + T + 4 * q;
        int i = ti * OUTT + row;
        int j = tj * OUTT + 4 * q;
        if (i >= NV) continue;
        float4 v = ld4s(src + IDX(li, lj));
        if (VOUT) {
            if (j + 3 < NV) {
                *reinterpret_cast<float4*>(uout + bO + (size_t)i * SP + j) = v;
            } else {
                float t[4] = {v.x, v.y, v.z, v.w};
                #pragma unroll
                for (int m = 0; m < 4; ++m)
                    if (j + m < NV) uout[bO + (size_t)i * SP + j + m] = t[m];
            }
        } else {
            float t[4] = {v.x, v.y, v.z, v.w};
            #pragma unroll
            for (int m = 0; m < 4; ++m)
                if (j + m < NV) uout[bO + (size_t)i * NV + j + m] = t[m];
        }
    }
}

// ---------------------------------------------------------------------------
extern "C" void kernel_launch(void* const* d_in, const int* in_sizes, int n_in,
                              void* d_out, int out_size) {
    const float* pre   = (const float*)d_in[0];   // (8,1,1022,1022)
    const float* f     = (const float*)d_in[1];   // (8,1,1024,1024)
    const float* kappa = (const float*)d_in[2];   // (8,1,1024,1024)
    float* out = (float*)d_out;                   // (8,1,1022,1022)

    float *A, *B;
    cudaGetSymbolAddress((void**)&A, g_bufA);
    cudaGetSymbolAddress((void**)&B, g_bufB);

    cudaFuncSetAttribute(fused_kernel<false, true>,
                         cudaFuncAttributeMaxDynamicSharedMemorySize, SMEM_BYTES);
    cudaFuncSetAttribute(fused_kernel<true, true>,
                         cudaFuncAttributeMaxDynamicSharedMemorySize, SMEM_BYTES);
    cudaFuncSetAttribute(fused_kernel<true, false>,
                         cudaFuncAttributeMaxDynamicSharedMemorySize, SMEM_BYTES);

    dim3 blk(16, 16, 1);
    dim3 grd(NT, NT, 8);

    // 16 sweeps = 4 fused kernels of T=4
    fused_kernel<false, true><<<grd, blk, SMEM_BYTES>>>(pre, A, kappa, f);
    fused_kernel<true,  true><<<grd, blk, SMEM_BYTES>>>(A,   B, kappa, f);
    fused_kernel<true,  true><<<grd, blk, SMEM_BYTES>>>(B,   A, kappa, f);
    fused_kernel<true, false><<<grd, blk, SMEM_BYTES>>>(A, out, kappa, f);
}

// round 5
// speedup vs baseline: 1.1593x; 1.1593x over previous
#include <cuda_runtime.h>

#define NV 1022            // interior size
#define GV 1024            // full grid
#define SP 1024            // padded scratch row stride

#define T    4             // fused sweeps per kernel
#define CRH  32            // compute-region rows per tile
#define CRW  64            // compute-region cols per tile
#define OUTR 24            // valid output rows = CRH - 2T
#define OUTC 56            // valid output cols = CRW - 2T
#define NTR  43            // ceil(1022/24)
#define NTC  19            // ceil(1022/56)

#define UH 34              // smem tile rows (CRH + 2 ring)
#define UW 72              // smem row stride (floats)
#define USZ (UH * UW)      // 2448 floats

#define HH2 (2.0f / (1023.0f * 1023.0f))   // 2*H^2

#define IDX(r, c) ((r) * UW + (c))

__device__ __align__(256) float g_bufA[8 * NV * SP];
__device__ __align__(256) float g_bufB[8 * NV * SP];

__device__ __forceinline__ float4 ld4g(const float* p) {
    return *reinterpret_cast<const float4*>(p);
}
__device__ __forceinline__ float4 ld4s(const float* p) {
    return *reinterpret_cast<const float4*>(p);
}
__device__ __forceinline__ void st4s(float* p, float4 v) {
    *reinterpret_cast<float4*>(p) = v;
}

// ---------------------------------------------------------------------------
// Fused 4-sweep Jacobi tile kernel, 512 threads, 1x4 points per thread.
//   smem u:  (li,lj) <-> interior (gi0-1+li, gj0-4+lj),  li in [0,34), lj in [0,72)
//   smem k:  (r,c)   <-> full     (gi0+r,   gj0+c),      r in [0,34), c in [0,68)
// Computed rows li=1..32; ring rows 0,33 and cols outside [4+s,67-s] go stale,
// but the emitted region (li 5..28, lj 8..63) is always within the valid cone.
// ---------------------------------------------------------------------------
template<bool VIN, bool VOUT>
__global__ __launch_bounds__(512, 2)
void fused_kernel(const float* __restrict__ uin,
                  float*       __restrict__ uout,
                  const float* __restrict__ kappa,
                  const float* __restrict__ f)
{
    __shared__ float U0[USZ];
    __shared__ float U1[USZ];
    __shared__ float KS[USZ];

    const int tx = threadIdx.x;          // 0..15
    const int ty = threadIdx.y;          // 0..31
    const int tid = ty * 16 + tx;
    const int tj = blockIdx.x, ti = blockIdx.y, b = blockIdx.z;

    const int gi0 = ti * OUTR - T;       // compute-region origin (interior coords)
    const int gj0 = tj * OUTC - T;       // multiple of 4

    const size_t bK = (size_t)b * GV * GV;
    const size_t bU = VIN  ? (size_t)b * NV * SP : (size_t)b * NV * NV;
    const size_t bO = VOUT ? (size_t)b * NV * SP : (size_t)b * NV * NV;

    // ---- cooperative load: kappa tile (34 x 68, float4 groups) ----
    for (int idx = tid; idx < UH * 17; idx += 512) {
        int r = idx / 17, q = idx % 17;
        int c  = 4 * q;
        int fr = gi0 + r;
        int fc = gj0 + c;
        float4 v;
        if (fr >= 0 && fr < GV && fc >= 0 && fc + 3 < GV) {
            v = ld4g(kappa + bK + (size_t)fr * GV + fc);
        } else {
            float t[4];
            #pragma unroll
            for (int m = 0; m < 4; ++m) {
                int cc = fc + m;
                t[m] = (fr >= 0 && fr < GV && cc >= 0 && cc < GV)
                       ? kappa[bK + (size_t)fr * GV + cc] : 0.0f;
            }
            v = make_float4(t[0], t[1], t[2], t[3]);
        }
        st4s(KS + IDX(r, c), v);
    }

    // ---- cooperative load: u0 tile (34 x 72) ----
    for (int idx = tid; idx < UH * 18; idx += 512) {
        int li = idx / 18, q = idx % 18;
        int lj = 4 * q;
        int i = gi0 - 1 + li;
        int j = gj0 - 4 + lj;
        float4 v;
        if (VIN && i >= 0 && i < NV && j >= 0 && j + 3 < NV) {
            v = ld4g(uin + bU + (size_t)i * SP + j);
        } else {
            float t[4];
            #pragma unroll
            for (int m = 0; m < 4; ++m) {
                int jj = j + m;
                t[m] = (i >= 0 && i < NV && jj >= 0 && jj < NV)
                       ? uin[bU + (size_t)i * (VIN ? SP : NV) + jj] : 0.0f;
            }
            v = make_float4(t[0], t[1], t[2], t[3]);
        }
        st4s(U0 + IDX(li, lj), v);
    }

    __syncthreads();

    // ---- per-thread coefficients (registers, once per kernel) ----
    const int li  = 1 + ty;              // owned row
    const int lj0 = 4 + 4 * tx;          // owned cols lj0..lj0+3

    float cN[4], cS[4], cW[4], cE[4], fp[4];
    {
        const int i = gi0 - 1 + li;      // interior row
        #pragma unroll
        for (int cc = 0; cc < 4; ++cc) {
            int c = lj0 + cc - 3;        // kappa-tile col
            int j = gj0 + c - 1;         // interior col
            bool valid = (i >= 0 && i < NV && j >= 0 && j < NV);
            if (valid) {
                float kc = KS[IDX(li,     c)];
                float kn = KS[IDX(li - 1, c)];
                float ks = KS[IDX(li + 1, c)];
                float kw = KS[IDX(li,     c - 1)];
                float ke = KS[IDX(li,     c + 1)];
                float aN = kc + kn, aS = kc + ks, aW = kc + kw, aE = kc + ke;
                float inv = __frcp_rn((aN + aS) + (aW + aE));
                cN[cc] = aN * inv;
                cS[cc] = aS * inv;
                cW[cc] = aW * inv;
                cE[cc] = aE * inv;
                fp[cc] = f[bK + (size_t)(i + 1) * GV + (j + 1)] * (HH2 * inv);
            } else {
                cN[cc] = cS[cc] = cW[cc] = cE[cc] = 0.0f;
                fp[cc] = 0.0f;
            }
        }
    }

    // ---- T fused sweeps in shared memory ----
    float* src = U0;
    float* dst = U1;
    #pragma unroll
    for (int s = 0; s < T; ++s) {
        float4 up = ld4s(src + IDX(li - 1, lj0));
        float4 ce = ld4s(src + IDX(li,     lj0));
        float4 dn = ld4s(src + IDX(li + 1, lj0));
        float  cl = src[IDX(li, lj0 - 1)];
        float  cr = src[IDX(li, lj0 + 4)];

        float4 r;
        r.x = fmaf(cN[0], up.x, fp[0]);
        r.x = fmaf(cS[0], dn.x, r.x);
        r.x = fmaf(cW[0], cl,   r.x);
        r.x = fmaf(cE[0], ce.y, r.x);

        r.y = fmaf(cN[1], up.y, fp[1]);
        r.y = fmaf(cS[1], dn.y, r.y);
        r.y = fmaf(cW[1], ce.x, r.y);
        r.y = fmaf(cE[1], ce.z, r.y);

        r.z = fmaf(cN[2], up.z, fp[2]);
        r.z = fmaf(cS[2], dn.z, r.z);
        r.z = fmaf(cW[2], ce.y, r.z);
        r.z = fmaf(cE[2], ce.w, r.z);

        r.w = fmaf(cN[3], up.w, fp[3]);
        r.w = fmaf(cS[3], dn.w, r.w);
        r.w = fmaf(cW[3], ce.z, r.w);
        r.w = fmaf(cE[3], cr,   r.w);

        __syncthreads();                 // ensure all reads of src done
        st4s(dst + IDX(li, lj0), r);
        __syncthreads();                 // ensure dst complete before next sweep
        float* tmp = src; src = dst; dst = tmp;
    }

    // ---- write valid 24x56 region (li 5..28, lj 8..63) ----
    for (int idx = tid; idx < OUTR * 14; idx += 512) {
        int row = idx / 14, q = idx % 14;
        int lli = 1 + T + row;
        int llj = 4 + T + 4 * q;
        int i = ti * OUTR + row;
        int j = tj * OUTC + 4 * q;
        if (i >= NV) continue;
        float4 v = ld4s(src + IDX(lli, llj));
        if (VOUT && j + 3 < NV) {
            *reinterpret_cast<float4*>(uout + bO + (size_t)i * SP + j) = v;
        } else {
            float t[4] = {v.x, v.y, v.z, v.w};
            #pragma unroll
            for (int m = 0; m < 4; ++m)
                if (j + m < NV) uout[bO + (size_t)i * (VOUT ? SP : NV) + j + m] = t[m];
        }
    }
}

// ---------------------------------------------------------------------------
extern "C" void kernel_launch(void* const* d_in, const int* in_sizes, int n_in,
                              void* d_out, int out_size) {
    const float* pre   = (const float*)d_in[0];   // (8,1,1022,1022)
    const float* f     = (const float*)d_in[1];   // (8,1,1024,1024)
    const float* kappa = (const float*)d_in[2];   // (8,1,1024,1024)
    float* out = (float*)d_out;                   // (8,1,1022,1022)

    float *A, *B;
    cudaGetSymbolAddress((void**)&A, g_bufA);
    cudaGetSymbolAddress((void**)&B, g_bufB);

    dim3 blk(16, 32, 1);
    dim3 grd(NTC, NTR, 8);

    // 16 sweeps = 4 fused kernels of T=4
    fused_kernel<false, true><<<grd, blk>>>(pre, A, kappa, f);
    fused_kernel<true,  true><<<grd, blk>>>(A,   B, kappa, f);
    fused_kernel<true,  true><<<grd, blk>>>(B,   A, kappa, f);
    fused_kernel<true, false><<<grd, blk>>>(A, out, kappa, f);
}

// round 10
// speedup vs baseline: 1.2687x; 1.0944x over previous
#include <cuda_runtime.h>

#define NV 1022            // interior size
#define GV 1024            // full grid
#define SP 1024            // padded scratch row stride

#define T    4             // fused sweeps per kernel
#define OUTR 24            // valid output rows per tile
#define OUTC 56            // valid output cols per tile
#define NTR  43            // ceil(1022/24)
#define NTC  19            // ceil(1022/56)
#define NTILES (8 * NTR * NTC)

#define UH 34              // smem u rows
#define UW 72              // smem u row stride
#define KW 68              // smem kappa/f row stride
#define USZ (UH * UW)      // 2448
#define KSZ (UH * KW)      // 2312

#define HH2 (2.0f / (1023.0f * 1023.0f))   // 2*H^2

__device__ __align__(256) float g_bufA[8 * NV * SP];
__device__ __align__(256) float g_bufB[8 * NV * SP];

// ---------------------------------------------------------------------------
__device__ __forceinline__ unsigned s2u(const void* p) {
    unsigned r;
    asm("{ .reg .u64 t; cvta.to.shared.u64 t, %1; cvt.u32.u64 %0, t; }"
        : "=r"(r) : "l"(p));
    return r;
}
__device__ __forceinline__ void cp16(float* dst, const float* src, bool inb) {
    int sz = inb ? 16 : 0;
    asm volatile("cp.async.ca.shared.global [%0], [%1], 16, %2;"
                 :: "r"(s2u(dst)), "l"(src), "r"(sz) : "memory");
}
__device__ __forceinline__ void cp4(float* dst, const float* src, bool inb) {
    int sz = inb ? 4 : 0;
    asm volatile("cp.async.ca.shared.global [%0], [%1], 4, %2;"
                 :: "r"(s2u(dst)), "l"(src), "r"(sz) : "memory");
}
#define CP_COMMIT() asm volatile("cp.async.commit_group;" ::: "memory")
#define CP_WAIT0()  asm volatile("cp.async.wait_group 0;"  ::: "memory")

// ---------------------------------------------------------------------------
// Async prefetch of one tile's u, kappa, f into smem. No barriers inside.
// Caller always commits a group (even when t >= NTILES).
// ---------------------------------------------------------------------------
template<bool VIN>
__device__ __forceinline__
void prefetch_tile(int t, float* UL, float* KS, float* FS,
                   const float* __restrict__ uin,
                   const float* __restrict__ kappa,
                   const float* __restrict__ f, int tid)
{
    if (t >= NTILES) return;
    int b  = t / (NTR * NTC);
    int r2 = t - b * (NTR * NTC);
    int ti = r2 / NTC, tj = r2 - ti * NTC;
    int gi0 = ti * OUTR - T;
    int gj0 = tj * OUTC - T;

    const size_t bK = (size_t)b * GV * GV;

    // kappa + f tiles: 34 x 68, 16B chunks (cols always 4-aligned in-grid)
    for (int idx = tid; idx < UH * 17; idx += 512) {
        int r = idx / 17, q = idx - r * 17;
        int c  = 4 * q;
        int fr = gi0 + r, fc = gj0 + c;
        bool inb = (fr >= 0 && fr < GV && fc >= 0 && fc < GV);
        size_t off = bK + (size_t)(inb ? fr : 0) * GV + (inb ? fc : 0);
        cp16(KS + r * KW + c, kappa + off, inb);
        cp16(FS + r * KW + c, f     + off, inb);
    }

    // u tile: 34 x 72
    if (VIN) {
        const size_t bU = (size_t)b * NV * SP;
        for (int idx = tid; idx < UH * 18; idx += 512) {
            int li = idx / 18, q = idx - li * 18;
            int lj = 4 * q;
            int i = gi0 - 1 + li, j = gj0 - 4 + lj;
            // padded rows: cols 1022..1023 exist and are zero, so j<=1020 OK
            bool inb = (i >= 0 && i < NV && j >= 0 && j < NV);
            cp16(UL + li * UW + lj,
                 uin + bU + (size_t)(inb ? i : 0) * SP + (inb ? j : 0), inb);
        }
    } else {
        const size_t bU = (size_t)b * NV * NV;
        for (int idx = tid; idx < UH * 18; idx += 512) {
            int li = idx / 18, q = idx - li * 18;
            int lj = 4 * q;
            int i = gi0 - 1 + li, j = gj0 - 4 + lj;
            #pragma unroll
            for (int m = 0; m < 4; ++m) {
                int jj = j + m;
                bool inb = (i >= 0 && i < NV && jj >= 0 && jj < NV);
                cp4(UL + li * UW + lj + m,
                    uin + bU + (size_t)(inb ? i : 0) * NV + (inb ? jj : 0), inb);
            }
        }
    }
}

// ---------------------------------------------------------------------------
// Persistent fused kernel: grid-stride over tiles, cp.async double-buffered.
// smem u map:  (li,lj) <-> interior (gi0-1+li, gj0-4+lj)
// smem k/f map:(r,c)   <-> full     (gi0+r,   gj0+c)
// ---------------------------------------------------------------------------
template<bool VIN, bool VOUT>
__global__ __launch_bounds__(512, 2)
void fused_kernel(const float* __restrict__ uin,
                  float*       __restrict__ uout,
                  const float* __restrict__ kappa,
                  const float* __restrict__ f)
{
    __shared__ float SM[3 * USZ + 2 * KSZ];   // 47872 bytes
    float* UL0 = SM;
    float* UL1 = SM + USZ;
    float* USC = SM + 2 * USZ;
    float* KS  = SM + 3 * USZ;
    float* FS  = KS + KSZ;

    const int tid = threadIdx.x;
    const int tx = tid & 15;            // 0..15
    const int ty = tid >> 4;            // 0..31
    const int nb = gridDim.x;
    const int iters = (NTILES + nb - 1) / nb;

    // prologue: prefetch first tile
    prefetch_tile<VIN>(blockIdx.x, UL0, KS, FS, uin, kappa, f, tid);
    CP_COMMIT();

    const int li  = 1 + ty;             // owned row
    const int lj0 = 4 + 4 * tx;         // owned cols lj0..lj0+3

    for (int k = 0; k < iters; ++k) {
        int t = blockIdx.x + k * nb;
        bool active = (t < NTILES);
        float* Ua = (k & 1) ? UL1 : UL0;
        float* Ub = (k & 1) ? UL0 : UL1;

        CP_WAIT0();
        __syncthreads();                 // tile-k data visible block-wide

        // ---- coefficients (registers) from KS/FS ----
        int b = 0, ti = 0, tj = 0, gi0 = 0, gj0 = 0;
        float cN[4], cS[4], cW[4], cE[4], fp[4];
        if (active) {
            b  = t / (NTR * NTC);
            int r2 = t - b * (NTR * NTC);
            ti = r2 / NTC; tj = r2 - ti * NTC;
            gi0 = ti * OUTR - T; gj0 = tj * OUTC - T;
            const int i = gi0 - 1 + li;
            #pragma unroll
            for (int cc = 0; cc < 4; ++cc) {
                int c = lj0 + cc - 3;
                int j = gj0 + c - 1;
                bool valid = (i >= 0 && i < NV && j >= 0 && j < NV);
                float kc = KS[li * KW + c];
                float kn = KS[(li - 1) * KW + c];
                float ks = KS[(li + 1) * KW + c];
                float kw = KS[li * KW + c - 1];
                float ke = KS[li * KW + c + 1];
                float aN = kc + kn, aS = kc + ks, aW = kc + kw, aE = kc + ke;
                float inv = __frcp_rn((aN + aS) + (aW + aE));
                cN[cc] = valid ? aN * inv : 0.0f;
                cS[cc] = valid ? aS * inv : 0.0f;
                cW[cc] = valid ? aW * inv : 0.0f;
                cE[cc] = valid ? aE * inv : 0.0f;
                fp[cc] = valid ? FS[li * KW + c] * (HH2 * inv) : 0.0f;
            }
        } else {
            #pragma unroll
            for (int cc = 0; cc < 4; ++cc) {
                cN[cc] = cS[cc] = cW[cc] = cE[cc] = fp[cc] = 0.0f;
            }
        }

        __syncthreads();                 // KS/FS reads done before overwrite

        // ---- prefetch next tile (overlaps the sweeps below) ----
        prefetch_tile<VIN>(blockIdx.x + (k + 1) * nb, Ub, KS, FS,
                           uin, kappa, f, tid);
        CP_COMMIT();

        // ---- T sweeps, ping-pong Ua <-> USC, one barrier per sweep ----
        float* src = Ua;
        float* dst = USC;
        #pragma unroll
        for (int s = 0; s < T; ++s) {
            float4 up = *(const float4*)(src + (li - 1) * UW + lj0);
            float4 ce = *(const float4*)(src + li * UW + lj0);
            float4 dn = *(const float4*)(src + (li + 1) * UW + lj0);
            float  cl = src[li * UW + lj0 - 1];
            float  cr = src[li * UW + lj0 + 4];

            float4 r;
            r.x = fmaf(cN[0], up.x, fp[0]);
            r.x = fmaf(cS[0], dn.x, r.x);
            r.x = fmaf(cW[0], cl,   r.x);
            r.x = fmaf(cE[0], ce.y, r.x);

            r.y = fmaf(cN[1], up.y, fp[1]);
            r.y = fmaf(cS[1], dn.y, r.y);
            r.y = fmaf(cW[1], ce.x, r.y);
            r.y = fmaf(cE[1], ce.z, r.y);

            r.z = fmaf(cN[2], up.z, fp[2]);
            r.z = fmaf(cS[2], dn.z, r.z);
            r.z = fmaf(cW[2], ce.y, r.z);
            r.z = fmaf(cE[2], ce.w, r.z);

            r.w = fmaf(cN[3], up.w, fp[3]);
            r.w = fmaf(cS[3], dn.w, r.w);
            r.w = fmaf(cW[3], ce.z, r.w);
            r.w = fmaf(cE[3], cr,   r.w);

            *(float4*)(dst + li * UW + lj0) = r;
            __syncthreads();
            float* tmp = src; src = dst; dst = tmp;
        }
        // T even -> final result in Ua

        // ---- emit valid 24x56 region (li 5..28, lj 8..63) ----
        if (active) {
            const size_t bO = VOUT ? (size_t)b * NV * SP : (size_t)b * NV * NV;
            for (int idx = tid; idx < OUTR * 14; idx += 512) {
                int row = idx / 14, q = idx - row * 14;
                int lli = 1 + T + row;
                int llj = 4 + T + 4 * q;
                int i = ti * OUTR + row;
                int j = tj * OUTC + 4 * q;
                if (i >= NV) continue;
                float4 v = *(const float4*)(Ua + lli * UW + llj);
                if (VOUT && j + 3 < NV) {
                    *(float4*)(uout + bO + (size_t)i * SP + j) = v;
                } else {
                    float tv[4] = {v.x, v.y, v.z, v.w};
                    #pragma unroll
                    for (int m = 0; m < 4; ++m)
                        if (j + m < NV)
                            uout[bO + (size_t)i * (VOUT ? SP : NV) + j + m] = tv[m];
                }
            }
        }
        // next iteration's top barrier orders epilogue reads vs. reuse
    }
}

// ---------------------------------------------------------------------------
extern "C" void kernel_launch(void* const* d_in, const int* in_sizes, int n_in,
                              void* d_out, int out_size) {
    const float* pre   = (const float*)d_in[0];   // (8,1,1022,1022)
    const float* f     = (const float*)d_in[1];   // (8,1,1024,1024)
    const float* kappa = (const float*)d_in[2];   // (8,1,1024,1024)
    float* out = (float*)d_out;                   // (8,1,1022,1022)

    float *A, *B;
    cudaGetSymbolAddress((void**)&A, g_bufA);
    cudaGetSymbolAddress((void**)&B, g_bufB);

    // allow 2 x 47.9KB smem per SM
    cudaFuncSetAttribute(fused_kernel<false, true>,
        cudaFuncAttributePreferredSharedMemoryCarveout, 100);
    cudaFuncSetAttribute(fused_kernel<true, true>,
        cudaFuncAttributePreferredSharedMemoryCarveout, 100);
    cudaFuncSetAttribute(fused_kernel<true, false>,
        cudaFuncAttributePreferredSharedMemoryCarveout, 100);

    int dev = 0, nsm = 148;
    cudaGetDevice(&dev);
    cudaDeviceGetAttribute(&nsm, cudaDevAttrMultiProcessorCount, dev);
    int nblocks = 2 * nsm;

    dim3 blk(512, 1, 1);
    dim3 grd(nblocks, 1, 1);

    // 16 sweeps = 4 fused kernels of T=4
    fused_kernel<false, true><<<grd, blk>>>(pre, A, kappa, f);
    fused_kernel<true,  true><<<grd, blk>>>(A,   B, kappa, f);
    fused_kernel<true,  true><<<grd, blk>>>(B,   A, kappa, f);
    fused_kernel<true, false><<<grd, blk>>>(A, out, kappa, f);
}